// round 6
// baseline (speedup 1.0000x reference)
#include <cuda_runtime.h>

#define BATCH 16
#define HW (1 << 20)
#define CB 4096                 // coarse bins (q >> 4)
#define FBITS 4                 // fine bins = 16 (q & 15)
#define CHUNKS 64
#define NT 256

// percentile ranks, n = 1048576 (linear interp):
// blk: 0.25*v[10485] + 0.75*v[10486] ; wht: 0.75*v[1038089] + 0.25*v[1038090]
#define RANK0 10485u
#define RANK1 10486u
#define RANK2 1038089u
#define RANK3 1038090u

// ---------------- device scratch ----------------
__device__ unsigned short g_Y16[(size_t)BATCH * HW];   // 32 MB quantized luma
__device__ unsigned g_hist[BATCH][CB];                 // coarse hists
__device__ unsigned g_hist2[BATCH][4][16];             // fine hists (tiny)
__device__ int      g_tbin[BATCH][4];
__device__ int      g_trank[BATCH][4];
__device__ float    g_blk[BATCH];
__device__ float    g_mult[BATCH];
__device__ unsigned g_done1[BATCH];                    // yhist done counters
__device__ unsigned g_done2[BATCH];                    // fine done counters

// ------------- kernel 1: Y16 + coarse hist; last CTA per batch does coarse select -------------
__global__ void __launch_bounds__(NT) k_yhist(const float* __restrict__ img,
                                              const float* __restrict__ mat) {
    __shared__ unsigned sh[CB];
    __shared__ unsigned s_last;
    const int b = blockIdx.y;
    const int chunk = blockIdx.x;
    const int tid = threadIdx.x;

    if (blockIdx.x == 0 && tid < 64)
        ((unsigned*)g_hist2[b])[tid] = 0u;

    for (int j = tid; j < CB; j += NT) sh[j] = 0u;
    __syncthreads();

    const float c0 = mat[0], c1 = mat[1], c2 = mat[2];
    const size_t base = (size_t)b * 3 * HW;
    const float4* __restrict__ R  = (const float4*)(img + base);
    const float4* __restrict__ G  = (const float4*)(img + base + HW);
    const float4* __restrict__ Bc = (const float4*)(img + base + 2 * (size_t)HW);
    uint2* __restrict__ Y = (uint2*)(g_Y16 + (size_t)b * HW);

    const int per_cta = (HW / 4) / CHUNKS;   // 4096 float4
    const int off = chunk * per_cta;

    #pragma unroll 4
    for (int i = tid; i < per_cta; i += NT) {
        float4 r = __ldcs(R + off + i);       // use-once stream: evict-first
        float4 g = __ldcs(G + off + i);
        float4 v = __ldcs(Bc + off + i);
        float y0 = c0 * r.x + c1 * g.x + c2 * v.x;
        float y1 = c0 * r.y + c1 * g.y + c2 * v.y;
        float y2 = c0 * r.z + c1 * g.z + c2 * v.z;
        float y3 = c0 * r.w + c1 * g.w + c2 * v.w;
        unsigned q0 = min((unsigned)(y0 * 65536.0f), 65535u);
        unsigned q1 = min((unsigned)(y1 * 65536.0f), 65535u);
        unsigned q2 = min((unsigned)(y2 * 65536.0f), 65535u);
        unsigned q3 = min((unsigned)(y3 * 65536.0f), 65535u);
        uint2 st;
        st.x = q0 | (q1 << 16);
        st.y = q2 | (q3 << 16);
        Y[off + i] = st;
        atomicAdd(&sh[q0 >> FBITS], 1u);
        atomicAdd(&sh[q1 >> FBITS], 1u);
        atomicAdd(&sh[q2 >> FBITS], 1u);
        atomicAdd(&sh[q3 >> FBITS], 1u);
    }
    __syncthreads();

    for (int j = tid; j < CB; j += NT) {
        unsigned v = sh[j];
        if (v) atomicAdd(&g_hist[b][j], v);
    }

    // ---- last CTA of this batch performs the coarse select ----
    __threadfence();
    __syncthreads();
    if (tid == 0) {
        unsigned old = atomicAdd(&g_done1[b], 1u);
        s_last = (old == CHUNKS - 1) ? 1u : 0u;
    }
    __syncthreads();
    if (!s_last) return;
    if (tid == 0) g_done1[b] = 0u;            // reset for next replay

    // reuse sh[0..NT) as psum
    const unsigned* __restrict__ h = g_hist[b];
    const int W = CB / NT;                    // 16
    const int sbase = tid * W;
    unsigned local = 0;
    #pragma unroll
    for (int j = 0; j < W; j++) local += h[sbase + j];
    sh[tid] = local;
    __syncthreads();
    if (tid == 0) {
        unsigned cum = 0;
        for (int i = 0; i < NT; i++) { unsigned c = sh[i]; sh[i] = cum; cum += c; }
    }
    __syncthreads();
    const unsigned pre = sh[tid];

    const unsigned ranks[4] = {RANK0, RANK1, RANK2, RANK3};
    #pragma unroll
    for (int t = 0; t < 4; t++) {
        unsigned r = ranks[t];
        if (r >= pre && r < pre + local) {
            unsigned cum = pre;
            for (int j = 0; j < W; j++) {
                unsigned c = h[sbase + j];
                if (r < cum + c) {
                    g_tbin[b][t] = sbase + j;
                    g_trank[b][t] = (int)(r - cum);
                    break;
                }
                cum += c;
            }
        }
    }
}

// ------------- kernel 2: fine counts; last CTA per batch computes blk/mult -------------
__global__ void __launch_bounds__(NT) k_fine() {
    __shared__ unsigned sf[64];
    __shared__ int stb[4];
    __shared__ unsigned s_last;
    __shared__ float s_vals[4];
    const int b = blockIdx.y;
    const int tid = threadIdx.x;

    if (tid < 64) sf[tid] = 0u;
    if (tid < 4) stb[tid] = g_tbin[b][tid];
    __syncthreads();
    const int t0 = stb[0], t1 = stb[1], t2 = stb[2], t3 = stb[3];

    const uint4* __restrict__ Y = (const uint4*)(g_Y16 + (size_t)b * HW);
    const int per_cta = (HW / 8) / CHUNKS;           // 2048 uint4
    const int off = blockIdx.x * per_cta;

    #pragma unroll 2
    for (int i = tid; i < per_cta; i += NT) {
        uint4 x = Y[off + i];
        unsigned w[4] = {x.x, x.y, x.z, x.w};
        #pragma unroll
        for (int k = 0; k < 4; k++) {
            unsigned vlo = w[k] & 0xffffu;
            unsigned vhi = w[k] >> 16;
            int clo = (int)(vlo >> FBITS);
            int chi = (int)(vhi >> FBITS);
            if (clo == t0) atomicAdd(&sf[ 0 + (vlo & 15u)], 1u);
            if (clo == t1) atomicAdd(&sf[16 + (vlo & 15u)], 1u);
            if (clo == t2) atomicAdd(&sf[32 + (vlo & 15u)], 1u);
            if (clo == t3) atomicAdd(&sf[48 + (vlo & 15u)], 1u);
            if (chi == t0) atomicAdd(&sf[ 0 + (vhi & 15u)], 1u);
            if (chi == t1) atomicAdd(&sf[16 + (vhi & 15u)], 1u);
            if (chi == t2) atomicAdd(&sf[32 + (vhi & 15u)], 1u);
            if (chi == t3) atomicAdd(&sf[48 + (vhi & 15u)], 1u);
        }
    }
    __syncthreads();
    if (tid < 64) {
        unsigned v = sf[tid];
        if (v) atomicAdd(&((unsigned*)g_hist2[b])[tid], v);
    }

    // ---- last CTA of this batch resolves the fine select & writes blk/mult ----
    __threadfence();
    __syncthreads();
    if (tid == 0) {
        unsigned old = atomicAdd(&g_done2[b], 1u);
        s_last = (old == CHUNKS - 1) ? 1u : 0u;
    }
    __syncthreads();
    if (!s_last) return;
    if (tid == 0) g_done2[b] = 0u;            // reset for next replay

    if (tid < 64) {
        const int t = tid >> 4;
        const int j = tid & 15;
        unsigned c = g_hist2[b][t][j];
        unsigned p = c;
        #pragma unroll
        for (int d = 1; d < 16; d <<= 1) {
            unsigned o = __shfl_up_sync(0xffffffffu, p, d, 16);
            if ((tid & 15) >= d) p += o;
        }
        unsigned pre = p - c;
        unsigned tr = (unsigned)g_trank[b][t];
        if (tr >= pre && tr < pre + c) {
            unsigned q = ((unsigned)stb[t] << FBITS) | (unsigned)j;
            s_vals[t] = ((float)q + 0.5f) * (1.0f / 65536.0f);
        }
    }
    __syncthreads();
    if (tid == 0) {
        float blk = 0.25f * s_vals[0] + 0.75f * s_vals[1];
        float wht = 0.75f * s_vals[2] + 0.25f * s_vals[3];
        g_blk[b] = blk;
        g_mult[b] = fminf(1.0f / (wht - blk), 1.5f);
    }
}

// ------------- kernel 3: apply. Zeroes g_hist for next replay. -------------
__global__ void __launch_bounds__(NT) k_apply(const float* __restrict__ img,
                                              float* __restrict__ out) {
    const int b = blockIdx.y;
    const int tid = threadIdx.x;

    // zero coarse hist for the next replay
    {
        int cta = blockIdx.y * gridDim.x + blockIdx.x;
        if (cta < 256) ((unsigned*)g_hist)[cta * 256 + tid] = 0u;
    }

    const float blk = g_blk[b];
    const float m = g_mult[b];

    const size_t base = (size_t)b * 3 * (HW / 4);
    const float4* __restrict__ in4 = (const float4*)img + base;
    float4* __restrict__ o4 = (float4*)out + base;
    const int n = 3 * (HW / 4);
    const int stride = gridDim.x * NT;

    for (int i = blockIdx.x * NT + tid; i < n; i += stride) {
        float4 v = in4[i];
        float4 r;
        r.x = fminf(fmaxf((v.x - blk) * m, 0.0f), 1.0f);
        r.y = fminf(fmaxf((v.y - blk) * m, 0.0f), 1.0f);
        r.z = fminf(fmaxf((v.z - blk) * m, 0.0f), 1.0f);
        r.w = fminf(fmaxf((v.w - blk) * m, 0.0f), 1.0f);
        o4[i] = r;
    }
}

// ---------------- launch ----------------
extern "C" void kernel_launch(void* const* d_in, const int* in_sizes, int n_in,
                              void* d_out, int out_size) {
    const float* img = (const float*)d_in[0];
    const float* mat = (const float*)d_in[1];
    float* out = (float*)d_out;

    dim3 gBig(CHUNKS, BATCH);
    k_yhist<<<gBig, NT>>>(img, mat);
    k_fine<<<gBig, NT>>>();
    dim3 gApply(384, BATCH);
    k_apply<<<gApply, NT>>>(img, out);
}

// round 7
// speedup vs baseline: 1.1647x; 1.1647x over previous
#include <cuda_runtime.h>

#define BATCH 16
#define HW (1 << 20)
#define CB 4096                 // coarse bins (q >> 4)
#define FBITS 4                 // fine bins = 16 (q & 15)
#define CHUNKS 64
#define NT 256

// percentile ranks, n = 1048576 (linear interp):
// blk: 0.25*v[10485] + 0.75*v[10486] ; wht: 0.75*v[1038089] + 0.25*v[1038090]
#define RANK0 10485u
#define RANK1 10486u
#define RANK2 1038089u
#define RANK3 1038090u

// ---------------- device scratch ----------------
__device__ unsigned short g_Y16[(size_t)BATCH * HW];   // 32 MB quantized luma
__device__ unsigned g_hist[BATCH][CB];                 // coarse hists
__device__ unsigned g_hist2[BATCH][4][16];             // fine hists (tiny)
__device__ int      g_tbin[BATCH][4];
__device__ int      g_trank[BATCH][4];
__device__ unsigned g_done1[BATCH];                    // yhist done counters

// ------------- kernel 1: Y16 + coarse hist (R2 hot loop, byte-identical) -------------
// Tail: last CTA per batch performs the coarse select (tid0-only fences).
__global__ void __launch_bounds__(NT) k_yhist(const float* __restrict__ img,
                                              const float* __restrict__ mat) {
    __shared__ unsigned sh[CB];
    __shared__ unsigned s_last;
    const int b = blockIdx.y;
    const int chunk = blockIdx.x;
    const int tid = threadIdx.x;

    if (blockIdx.x == 0 && tid < 64)
        ((unsigned*)g_hist2[b])[tid] = 0u;

    for (int j = tid; j < CB; j += NT) sh[j] = 0u;
    __syncthreads();

    const float c0 = mat[0], c1 = mat[1], c2 = mat[2];
    const size_t base = (size_t)b * 3 * HW;
    const float4* __restrict__ R  = (const float4*)(img + base);
    const float4* __restrict__ G  = (const float4*)(img + base + HW);
    const float4* __restrict__ Bc = (const float4*)(img + base + 2 * (size_t)HW);
    uint2* __restrict__ Y = (uint2*)(g_Y16 + (size_t)b * HW);

    const int per_cta = (HW / 4) / CHUNKS;   // 4096 float4
    const int off = chunk * per_cta;

    #pragma unroll 4
    for (int i = tid; i < per_cta; i += NT) {
        float4 r = R[off + i];
        float4 g = G[off + i];
        float4 v = Bc[off + i];
        float y0 = c0 * r.x + c1 * g.x + c2 * v.x;
        float y1 = c0 * r.y + c1 * g.y + c2 * v.y;
        float y2 = c0 * r.z + c1 * g.z + c2 * v.z;
        float y3 = c0 * r.w + c1 * g.w + c2 * v.w;
        unsigned q0 = min((unsigned)(y0 * 65536.0f), 65535u);
        unsigned q1 = min((unsigned)(y1 * 65536.0f), 65535u);
        unsigned q2 = min((unsigned)(y2 * 65536.0f), 65535u);
        unsigned q3 = min((unsigned)(y3 * 65536.0f), 65535u);
        uint2 st;
        st.x = q0 | (q1 << 16);
        st.y = q2 | (q3 << 16);
        Y[off + i] = st;
        atomicAdd(&sh[q0 >> FBITS], 1u);
        atomicAdd(&sh[q1 >> FBITS], 1u);
        atomicAdd(&sh[q2 >> FBITS], 1u);
        atomicAdd(&sh[q3 >> FBITS], 1u);
    }
    __syncthreads();

    for (int j = tid; j < CB; j += NT) {
        unsigned v = sh[j];
        if (v) atomicAdd(&g_hist[b][j], v);
    }

    // ---- last-CTA coarse select; fences confined to tid0 ----
    __syncthreads();                          // all hist atomics issued (CTA order)
    if (tid == 0) {
        __threadfence();                      // release (one thread, one CCTL)
        unsigned old = atomicAdd(&g_done1[b], 1u);
        s_last = (old == CHUNKS - 1) ? 1u : 0u;
        if (s_last) {
            g_done1[b] = 0u;                  // reset for next graph replay
            __threadfence();                  // acquire (last CTA only)
        }
    }
    __syncthreads();
    if (!s_last) return;

    // reuse sh[0..NT) as psum; read hist via L2 (__ldcg)
    const unsigned* __restrict__ h = g_hist[b];
    const int W = CB / NT;                    // 16
    const int sbase = tid * W;
    unsigned bins[W];
    unsigned local = 0;
    #pragma unroll
    for (int j = 0; j < W; j++) { bins[j] = __ldcg(h + sbase + j); local += bins[j]; }
    sh[tid] = local;
    __syncthreads();
    if (tid == 0) {
        unsigned cum = 0;
        for (int i = 0; i < NT; i++) { unsigned c = sh[i]; sh[i] = cum; cum += c; }
    }
    __syncthreads();
    const unsigned pre = sh[tid];

    const unsigned ranks[4] = {RANK0, RANK1, RANK2, RANK3};
    #pragma unroll
    for (int t = 0; t < 4; t++) {
        unsigned r = ranks[t];
        if (r >= pre && r < pre + local) {
            unsigned cum = pre;
            #pragma unroll
            for (int j = 0; j < W; j++) {
                unsigned c = bins[j];
                if (r < cum + c) {
                    g_tbin[b][t] = sbase + j;
                    g_trank[b][t] = (int)(r - cum);
                    break;
                }
                cum += c;
            }
        }
    }
}

// ------------- kernel 2: fine (4-bit) counts inside the 4 target coarse bins -------------
__global__ void __launch_bounds__(NT) k_fine() {
    __shared__ unsigned sf[64];
    __shared__ int stb[4];
    const int b = blockIdx.y;

    if (threadIdx.x < 64) sf[threadIdx.x] = 0u;
    if (threadIdx.x < 4) stb[threadIdx.x] = g_tbin[b][threadIdx.x];
    __syncthreads();
    const int t0 = stb[0], t1 = stb[1], t2 = stb[2], t3 = stb[3];

    const uint4* __restrict__ Y = (const uint4*)(g_Y16 + (size_t)b * HW);
    const int per_cta = (HW / 8) / CHUNKS;           // 2048 uint4
    const int off = blockIdx.x * per_cta;

    #pragma unroll 2
    for (int i = threadIdx.x; i < per_cta; i += NT) {
        uint4 x = Y[off + i];
        unsigned w[4] = {x.x, x.y, x.z, x.w};
        #pragma unroll
        for (int k = 0; k < 4; k++) {
            unsigned vlo = w[k] & 0xffffu;
            unsigned vhi = w[k] >> 16;
            int clo = (int)(vlo >> FBITS);
            int chi = (int)(vhi >> FBITS);
            if (clo == t0) atomicAdd(&sf[ 0 + (vlo & 15u)], 1u);
            if (clo == t1) atomicAdd(&sf[16 + (vlo & 15u)], 1u);
            if (clo == t2) atomicAdd(&sf[32 + (vlo & 15u)], 1u);
            if (clo == t3) atomicAdd(&sf[48 + (vlo & 15u)], 1u);
            if (chi == t0) atomicAdd(&sf[ 0 + (vhi & 15u)], 1u);
            if (chi == t1) atomicAdd(&sf[16 + (vhi & 15u)], 1u);
            if (chi == t2) atomicAdd(&sf[32 + (vhi & 15u)], 1u);
            if (chi == t3) atomicAdd(&sf[48 + (vhi & 15u)], 1u);
        }
    }
    __syncthreads();
    if (threadIdx.x < 64) {
        unsigned v = sf[threadIdx.x];
        if (v) atomicAdd(&((unsigned*)g_hist2[b])[threadIdx.x], v);
    }
}

// ------------- kernel 3: per-CTA redundant fine select, then apply. Zeroes g_hist. -------------
__global__ void __launch_bounds__(NT) k_apply(const float* __restrict__ img,
                                              float* __restrict__ out) {
    __shared__ float s_vals[4];
    __shared__ float s_bm[2];
    const int b = blockIdx.y;
    const int tid = threadIdx.x;

    // zero coarse hist for the next replay (yhist-tail select already consumed it)
    {
        int cta = blockIdx.y * gridDim.x + blockIdx.x;
        if (cta < 256) ((unsigned*)g_hist)[cta * 256 + tid] = 0u;
    }

    // redundant select: threads 0..63 = (target t = tid>>4, fine bin j = tid&15)
    if (tid < 64) {
        const int t = tid >> 4;
        const int j = tid & 15;
        unsigned c = g_hist2[b][t][j];
        unsigned p = c;
        #pragma unroll
        for (int d = 1; d < 16; d <<= 1) {
            unsigned o = __shfl_up_sync(0xffffffffu, p, d, 16);
            if ((tid & 15) >= d) p += o;
        }
        unsigned pre = p - c;
        unsigned tr = (unsigned)g_trank[b][t];
        if (tr >= pre && tr < pre + c) {
            unsigned q = ((unsigned)g_tbin[b][t] << FBITS) | (unsigned)j;
            s_vals[t] = ((float)q + 0.5f) * (1.0f / 65536.0f);
        }
    }
    __syncthreads();
    if (tid == 0) {
        float blk = 0.25f * s_vals[0] + 0.75f * s_vals[1];
        float wht = 0.75f * s_vals[2] + 0.25f * s_vals[3];
        s_bm[0] = blk;
        s_bm[1] = fminf(1.0f / (wht - blk), 1.5f);
    }
    __syncthreads();
    const float blk = s_bm[0];
    const float m = s_bm[1];

    const size_t base = (size_t)b * 3 * (HW / 4);
    const float4* __restrict__ in4 = (const float4*)img + base;
    float4* __restrict__ o4 = (float4*)out + base;
    const int n = 3 * (HW / 4);
    const int stride = gridDim.x * NT;

    for (int i = blockIdx.x * NT + tid; i < n; i += stride) {
        float4 v = in4[i];
        float4 r;
        r.x = fminf(fmaxf((v.x - blk) * m, 0.0f), 1.0f);
        r.y = fminf(fmaxf((v.y - blk) * m, 0.0f), 1.0f);
        r.z = fminf(fmaxf((v.z - blk) * m, 0.0f), 1.0f);
        r.w = fminf(fmaxf((v.w - blk) * m, 0.0f), 1.0f);
        o4[i] = r;
    }
}

// ---------------- launch ----------------
extern "C" void kernel_launch(void* const* d_in, const int* in_sizes, int n_in,
                              void* d_out, int out_size) {
    const float* img = (const float*)d_in[0];
    const float* mat = (const float*)d_in[1];
    float* out = (float*)d_out;

    dim3 gBig(CHUNKS, BATCH);
    k_yhist<<<gBig, NT>>>(img, mat);
    k_fine<<<gBig, NT>>>();
    dim3 gApply(384, BATCH);
    k_apply<<<gApply, NT>>>(img, out);
}

// round 8
// speedup vs baseline: 1.2701x; 1.0904x over previous
#include <cuda_runtime.h>

#define BATCH 16
#define HW (1 << 20)
#define CB 4096                 // coarse bins (q >> 4)
#define FBITS 4                 // fine bins = 16 (q & 15)
#define CHUNKS 64
#define NT 256

// percentile ranks, n = 1048576 (linear interp):
// blk: 0.25*v[10485] + 0.75*v[10486] ; wht: 0.75*v[1038089] + 0.25*v[1038090]
#define RANK0 10485u
#define RANK1 10486u
#define RANK2 1038089u
#define RANK3 1038090u

// ---------------- device scratch ----------------
__device__ unsigned short g_Y16[(size_t)BATCH * HW];   // 32 MB quantized luma
__device__ unsigned g_hist[BATCH][CB];                 // coarse hists
__device__ unsigned g_hist2[BATCH][4][16];             // fine hists (tiny)
__device__ int      g_tbin[BATCH][4];
__device__ int      g_trank[BATCH][4];
__device__ unsigned g_flag[BATCH];                     // coarse-select published flags

// ------------- kernel 1: Y16 + coarse hist (R2 hot loop, byte-identical) -------------
__global__ void __launch_bounds__(NT) k_yhist(const float* __restrict__ img,
                                              const float* __restrict__ mat) {
    __shared__ unsigned sh[CB];
    const int b = blockIdx.y;
    const int chunk = blockIdx.x;

    if (blockIdx.x == 0 && threadIdx.x < 64)
        ((unsigned*)g_hist2[b])[threadIdx.x] = 0u;

    for (int j = threadIdx.x; j < CB; j += NT) sh[j] = 0u;
    __syncthreads();

    const float c0 = mat[0], c1 = mat[1], c2 = mat[2];
    const size_t base = (size_t)b * 3 * HW;
    const float4* __restrict__ R  = (const float4*)(img + base);
    const float4* __restrict__ G  = (const float4*)(img + base + HW);
    const float4* __restrict__ Bc = (const float4*)(img + base + 2 * (size_t)HW);
    uint2* __restrict__ Y = (uint2*)(g_Y16 + (size_t)b * HW);

    const int per_cta = (HW / 4) / CHUNKS;   // 4096 float4
    const int off = chunk * per_cta;

    #pragma unroll 4
    for (int i = threadIdx.x; i < per_cta; i += NT) {
        float4 r = R[off + i];
        float4 g = G[off + i];
        float4 v = Bc[off + i];
        float y0 = c0 * r.x + c1 * g.x + c2 * v.x;
        float y1 = c0 * r.y + c1 * g.y + c2 * v.y;
        float y2 = c0 * r.z + c1 * g.z + c2 * v.z;
        float y3 = c0 * r.w + c1 * g.w + c2 * v.w;
        unsigned q0 = min((unsigned)(y0 * 65536.0f), 65535u);
        unsigned q1 = min((unsigned)(y1 * 65536.0f), 65535u);
        unsigned q2 = min((unsigned)(y2 * 65536.0f), 65535u);
        unsigned q3 = min((unsigned)(y3 * 65536.0f), 65535u);
        uint2 st;
        st.x = q0 | (q1 << 16);
        st.y = q2 | (q3 << 16);
        Y[off + i] = st;
        atomicAdd(&sh[q0 >> FBITS], 1u);
        atomicAdd(&sh[q1 >> FBITS], 1u);
        atomicAdd(&sh[q2 >> FBITS], 1u);
        atomicAdd(&sh[q3 >> FBITS], 1u);
    }
    __syncthreads();

    for (int j = threadIdx.x; j < CB; j += NT) {
        unsigned v = sh[j];
        if (v) atomicAdd(&g_hist[b][j], v);
    }
}

// ------------- kernel 2: fine counts; CTA.x==0 per batch is the coarse-select producer -------------
__global__ void __launch_bounds__(NT) k_fine() {
    __shared__ uint4 sy[(HW / 8) / CHUNKS];          // 2048 uint4 = 32 KB chunk stage
    __shared__ unsigned sf[64];
    __shared__ unsigned psum[NT];
    __shared__ int stb[4];
    const int b = blockIdx.y;
    const int tid = threadIdx.x;
    const int per_cta = (HW / 8) / CHUNKS;           // 2048 uint4
    const int off = blockIdx.x * per_cta;

    if (tid < 64) sf[tid] = 0u;

    if (blockIdx.x == 0) {
        // ---- producer: coarse select from L2-resident g_hist[b] ----
        const unsigned* __restrict__ h = g_hist[b];
        const int W = CB / NT;                       // 16
        const int sbase = tid * W;
        unsigned bins[CB / NT];
        unsigned local = 0;
        #pragma unroll
        for (int j = 0; j < W; j++) { bins[j] = __ldcg(h + sbase + j); local += bins[j]; }
        psum[tid] = local;
        __syncthreads();
        if (tid == 0) {
            unsigned cum = 0;
            for (int i = 0; i < NT; i++) { unsigned c = psum[i]; psum[i] = cum; cum += c; }
        }
        __syncthreads();
        const unsigned pre = psum[tid];

        const unsigned ranks[4] = {RANK0, RANK1, RANK2, RANK3};
        #pragma unroll
        for (int t = 0; t < 4; t++) {
            unsigned r = ranks[t];
            if (r >= pre && r < pre + local) {
                unsigned cum = pre;
                #pragma unroll
                for (int j = 0; j < W; j++) {
                    unsigned c = bins[j];
                    if (r < cum + c) {
                        g_tbin[b][t] = sbase + j;
                        g_trank[b][t] = (int)(r - cum);
                        stb[t] = sbase + j;
                        break;
                    }
                    cum += c;
                }
            }
        }
        __syncthreads();                             // tbin/trank stores issued
        if (tid == 0) {
            __threadfence();                         // 16 CTAs total: negligible
            g_flag[b] = 1u;
        }
        // producer stages its own chunk after publishing
        for (int i = tid; i < per_cta; i += NT)
            sy[i] = ((const uint4*)(g_Y16 + (size_t)b * HW))[off + i];
        __syncthreads();
    } else {
        // ---- consumer: prefetch chunk to smem FIRST (hides producer latency) ----
        const uint4* __restrict__ Y = (const uint4*)(g_Y16 + (size_t)b * HW);
        for (int i = tid; i < per_cta; i += NT)
            sy[i] = Y[off + i];
        if (tid == 0) {
            while (*(volatile unsigned*)&g_flag[b] == 0u) __nanosleep(64);
        }
        __syncthreads();                             // flag seen + smem stage complete
        if (tid < 4) stb[tid] = __ldcg(&g_tbin[b][tid]);
        __syncthreads();
    }

    const int t0 = stb[0], t1 = stb[1], t2 = stb[2], t3 = stb[3];

    #pragma unroll 2
    for (int i = tid; i < per_cta; i += NT) {
        uint4 x = sy[i];
        unsigned w[4] = {x.x, x.y, x.z, x.w};
        #pragma unroll
        for (int k = 0; k < 4; k++) {
            unsigned vlo = w[k] & 0xffffu;
            unsigned vhi = w[k] >> 16;
            int clo = (int)(vlo >> FBITS);
            int chi = (int)(vhi >> FBITS);
            if (clo == t0) atomicAdd(&sf[ 0 + (vlo & 15u)], 1u);
            if (clo == t1) atomicAdd(&sf[16 + (vlo & 15u)], 1u);
            if (clo == t2) atomicAdd(&sf[32 + (vlo & 15u)], 1u);
            if (clo == t3) atomicAdd(&sf[48 + (vlo & 15u)], 1u);
            if (chi == t0) atomicAdd(&sf[ 0 + (vhi & 15u)], 1u);
            if (chi == t1) atomicAdd(&sf[16 + (vhi & 15u)], 1u);
            if (chi == t2) atomicAdd(&sf[32 + (vhi & 15u)], 1u);
            if (chi == t3) atomicAdd(&sf[48 + (vhi & 15u)], 1u);
        }
    }
    __syncthreads();
    if (tid < 64) {
        unsigned v = sf[tid];
        if (v) atomicAdd(&((unsigned*)g_hist2[b])[tid], v);
    }
}

// ------------- kernel 3: per-CTA redundant fine select, then apply. Resets hist+flags. -------------
__global__ void __launch_bounds__(NT) k_apply(const float* __restrict__ img,
                                              float* __restrict__ out) {
    __shared__ float s_vals[4];
    __shared__ float s_bm[2];
    const int b = blockIdx.y;
    const int tid = threadIdx.x;

    // reset coarse hist + flags for the next replay (both fully consumed by k_fine)
    {
        int cta = blockIdx.y * gridDim.x + blockIdx.x;
        if (cta < 256) ((unsigned*)g_hist)[cta * 256 + tid] = 0u;
        if (cta == 256 && tid < BATCH) g_flag[tid] = 0u;
    }

    // redundant select: threads 0..63 = (target t = tid>>4, fine bin j = tid&15)
    if (tid < 64) {
        const int t = tid >> 4;
        const int j = tid & 15;
        unsigned c = g_hist2[b][t][j];
        unsigned p = c;
        #pragma unroll
        for (int d = 1; d < 16; d <<= 1) {
            unsigned o = __shfl_up_sync(0xffffffffu, p, d, 16);
            if ((tid & 15) >= d) p += o;
        }
        unsigned pre = p - c;
        unsigned tr = (unsigned)g_trank[b][t];
        if (tr >= pre && tr < pre + c) {
            unsigned q = ((unsigned)g_tbin[b][t] << FBITS) | (unsigned)j;
            s_vals[t] = ((float)q + 0.5f) * (1.0f / 65536.0f);
        }
    }
    __syncthreads();
    if (tid == 0) {
        float blk = 0.25f * s_vals[0] + 0.75f * s_vals[1];
        float wht = 0.75f * s_vals[2] + 0.25f * s_vals[3];
        s_bm[0] = blk;
        s_bm[1] = fminf(1.0f / (wht - blk), 1.5f);
    }
    __syncthreads();
    const float blk = s_bm[0];
    const float m = s_bm[1];

    const size_t base = (size_t)b * 3 * (HW / 4);
    const float4* __restrict__ in4 = (const float4*)img + base;
    float4* __restrict__ o4 = (float4*)out + base;
    const int n = 3 * (HW / 4);
    const int stride = gridDim.x * NT;

    for (int i = blockIdx.x * NT + tid; i < n; i += stride) {
        float4 v = in4[i];
        float4 r;
        r.x = fminf(fmaxf((v.x - blk) * m, 0.0f), 1.0f);
        r.y = fminf(fmaxf((v.y - blk) * m, 0.0f), 1.0f);
        r.z = fminf(fmaxf((v.z - blk) * m, 0.0f), 1.0f);
        r.w = fminf(fmaxf((v.w - blk) * m, 0.0f), 1.0f);
        o4[i] = r;
    }
}

// ---------------- launch ----------------
extern "C" void kernel_launch(void* const* d_in, const int* in_sizes, int n_in,
                              void* d_out, int out_size) {
    const float* img = (const float*)d_in[0];
    const float* mat = (const float*)d_in[1];
    float* out = (float*)d_out;

    dim3 gBig(CHUNKS, BATCH);
    k_yhist<<<gBig, NT>>>(img, mat);
    k_fine<<<gBig, NT>>>();
    dim3 gApply(384, BATCH);
    k_apply<<<gApply, NT>>>(img, out);
}

// round 9
// speedup vs baseline: 1.3003x; 1.0238x over previous
#include <cuda_runtime.h>

#define BATCH 16
#define HW (1 << 20)
#define CB 4096                 // coarse bins (q >> 4)
#define FBITS 4                 // fine bins = 16 (q & 15)
#define CHUNKS 64
#define NT 256

// percentile ranks, n = 1048576 (linear interp):
// blk: 0.25*v[10485] + 0.75*v[10486] ; wht: 0.75*v[1038089] + 0.25*v[1038090]
#define RANK0 10485u
#define RANK1 10486u
#define RANK2 1038089u
#define RANK3 1038090u

// ---------------- device scratch ----------------
__device__ unsigned short g_Y16[(size_t)BATCH * HW];   // 32 MB quantized luma
__device__ unsigned g_hist[BATCH][CB];                 // coarse hists
__device__ unsigned g_hist2[BATCH][4][16];             // fine hists (tiny)
__device__ int      g_tbin[BATCH][4];
__device__ int      g_trank[BATCH][4];
__device__ unsigned g_flag[BATCH];                     // coarse-select published flags

// ------------- kernel 1: Y16 + coarse hist (R2 hot loop, byte-identical) -------------
__global__ void __launch_bounds__(NT) k_yhist(const float* __restrict__ img,
                                              const float* __restrict__ mat) {
    __shared__ unsigned sh[CB];
    const int b = blockIdx.y;
    const int chunk = blockIdx.x;

    if (blockIdx.x == 0 && threadIdx.x < 64)
        ((unsigned*)g_hist2[b])[threadIdx.x] = 0u;

    for (int j = threadIdx.x; j < CB; j += NT) sh[j] = 0u;
    __syncthreads();

    const float c0 = mat[0], c1 = mat[1], c2 = mat[2];
    const size_t base = (size_t)b * 3 * HW;
    const float4* __restrict__ R  = (const float4*)(img + base);
    const float4* __restrict__ G  = (const float4*)(img + base + HW);
    const float4* __restrict__ Bc = (const float4*)(img + base + 2 * (size_t)HW);
    uint2* __restrict__ Y = (uint2*)(g_Y16 + (size_t)b * HW);

    const int per_cta = (HW / 4) / CHUNKS;   // 4096 float4
    const int off = chunk * per_cta;

    #pragma unroll 4
    for (int i = threadIdx.x; i < per_cta; i += NT) {
        float4 r = R[off + i];
        float4 g = G[off + i];
        float4 v = Bc[off + i];
        float y0 = c0 * r.x + c1 * g.x + c2 * v.x;
        float y1 = c0 * r.y + c1 * g.y + c2 * v.y;
        float y2 = c0 * r.z + c1 * g.z + c2 * v.z;
        float y3 = c0 * r.w + c1 * g.w + c2 * v.w;
        unsigned q0 = min((unsigned)(y0 * 65536.0f), 65535u);
        unsigned q1 = min((unsigned)(y1 * 65536.0f), 65535u);
        unsigned q2 = min((unsigned)(y2 * 65536.0f), 65535u);
        unsigned q3 = min((unsigned)(y3 * 65536.0f), 65535u);
        uint2 st;
        st.x = q0 | (q1 << 16);
        st.y = q2 | (q3 << 16);
        Y[off + i] = st;
        atomicAdd(&sh[q0 >> FBITS], 1u);
        atomicAdd(&sh[q1 >> FBITS], 1u);
        atomicAdd(&sh[q2 >> FBITS], 1u);
        atomicAdd(&sh[q3 >> FBITS], 1u);
    }
    __syncthreads();

    for (int j = threadIdx.x; j < CB; j += NT) {
        unsigned v = sh[j];
        if (v) atomicAdd(&g_hist[b][j], v);
    }
}

// ------------- kernel 2: fine counts, direct from global (R2 loop); CTA.x==0 = producer -------------
__global__ void __launch_bounds__(NT) k_fine() {
    __shared__ unsigned sf[64];
    __shared__ unsigned psum[NT];
    __shared__ int stb[4];
    const int b = blockIdx.y;
    const int tid = threadIdx.x;

    if (tid < 64) sf[tid] = 0u;

    if (blockIdx.x == 0) {
        // ---- producer: coarse select from L2-resident g_hist[b] ----
        const unsigned* __restrict__ h = g_hist[b];
        const int W = CB / NT;                       // 16
        const int sbase = tid * W;
        unsigned bins[CB / NT];
        unsigned local = 0;
        #pragma unroll
        for (int j = 0; j < W; j++) { bins[j] = __ldcg(h + sbase + j); local += bins[j]; }
        psum[tid] = local;
        __syncthreads();
        if (tid == 0) {
            unsigned cum = 0;
            for (int i = 0; i < NT; i++) { unsigned c = psum[i]; psum[i] = cum; cum += c; }
        }
        __syncthreads();
        const unsigned pre = psum[tid];

        const unsigned ranks[4] = {RANK0, RANK1, RANK2, RANK3};
        #pragma unroll
        for (int t = 0; t < 4; t++) {
            unsigned r = ranks[t];
            if (r >= pre && r < pre + local) {
                unsigned cum = pre;
                #pragma unroll
                for (int j = 0; j < W; j++) {
                    unsigned c = bins[j];
                    if (r < cum + c) {
                        g_tbin[b][t] = sbase + j;
                        g_trank[b][t] = (int)(r - cum);
                        stb[t] = sbase + j;
                        break;
                    }
                    cum += c;
                }
            }
        }
        __syncthreads();                             // tbin/trank stores issued
        if (tid == 0) {
            __threadfence();                         // 16 CTAs total: negligible
            g_flag[b] = 1u;
        }
        __syncthreads();
    } else {
        // ---- consumer: wait for producer's publication (few-us, launch-overlapped) ----
        if (tid == 0) {
            while (*(volatile unsigned*)&g_flag[b] == 0u) __nanosleep(64);
        }
        __syncthreads();
        if (tid < 4) stb[tid] = __ldcg(&g_tbin[b][tid]);
        __syncthreads();
    }

    const int t0 = stb[0], t1 = stb[1], t2 = stb[2], t3 = stb[3];

    const uint4* __restrict__ Y = (const uint4*)(g_Y16 + (size_t)b * HW);
    const int per_cta = (HW / 8) / CHUNKS;           // 2048 uint4
    const int off = blockIdx.x * per_cta;

    #pragma unroll 2
    for (int i = tid; i < per_cta; i += NT) {
        uint4 x = Y[off + i];
        unsigned w[4] = {x.x, x.y, x.z, x.w};
        #pragma unroll
        for (int k = 0; k < 4; k++) {
            unsigned vlo = w[k] & 0xffffu;
            unsigned vhi = w[k] >> 16;
            int clo = (int)(vlo >> FBITS);
            int chi = (int)(vhi >> FBITS);
            if (clo == t0) atomicAdd(&sf[ 0 + (vlo & 15u)], 1u);
            if (clo == t1) atomicAdd(&sf[16 + (vlo & 15u)], 1u);
            if (clo == t2) atomicAdd(&sf[32 + (vlo & 15u)], 1u);
            if (clo == t3) atomicAdd(&sf[48 + (vlo & 15u)], 1u);
            if (chi == t0) atomicAdd(&sf[ 0 + (vhi & 15u)], 1u);
            if (chi == t1) atomicAdd(&sf[16 + (vhi & 15u)], 1u);
            if (chi == t2) atomicAdd(&sf[32 + (vhi & 15u)], 1u);
            if (chi == t3) atomicAdd(&sf[48 + (vhi & 15u)], 1u);
        }
    }
    __syncthreads();
    if (tid < 64) {
        unsigned v = sf[tid];
        if (v) atomicAdd(&((unsigned*)g_hist2[b])[tid], v);
    }
}

// ------------- kernel 3: per-CTA redundant fine select, then apply. Resets hist+flags. -------------
__global__ void __launch_bounds__(NT) k_apply(const float* __restrict__ img,
                                              float* __restrict__ out) {
    __shared__ float s_vals[4];
    __shared__ float s_bm[2];
    const int b = blockIdx.y;
    const int tid = threadIdx.x;

    // reset coarse hist + flags for the next replay (both fully consumed by k_fine)
    {
        int cta = blockIdx.y * gridDim.x + blockIdx.x;
        if (cta < 256) ((unsigned*)g_hist)[cta * 256 + tid] = 0u;
        if (cta == 256 && tid < BATCH) g_flag[tid] = 0u;
    }

    // redundant select: threads 0..63 = (target t = tid>>4, fine bin j = tid&15)
    if (tid < 64) {
        const int t = tid >> 4;
        const int j = tid & 15;
        unsigned c = g_hist2[b][t][j];
        unsigned p = c;
        #pragma unroll
        for (int d = 1; d < 16; d <<= 1) {
            unsigned o = __shfl_up_sync(0xffffffffu, p, d, 16);
            if ((tid & 15) >= d) p += o;
        }
        unsigned pre = p - c;
        unsigned tr = (unsigned)g_trank[b][t];
        if (tr >= pre && tr < pre + c) {
            unsigned q = ((unsigned)g_tbin[b][t] << FBITS) | (unsigned)j;
            s_vals[t] = ((float)q + 0.5f) * (1.0f / 65536.0f);
        }
    }
    __syncthreads();
    if (tid == 0) {
        float blk = 0.25f * s_vals[0] + 0.75f * s_vals[1];
        float wht = 0.75f * s_vals[2] + 0.25f * s_vals[3];
        s_bm[0] = blk;
        s_bm[1] = fminf(1.0f / (wht - blk), 1.5f);
    }
    __syncthreads();
    const float blk = s_bm[0];
    const float m = s_bm[1];

    const size_t base = (size_t)b * 3 * (HW / 4);
    const float4* __restrict__ in4 = (const float4*)img + base;
    float4* __restrict__ o4 = (float4*)out + base;
    const int n = 3 * (HW / 4);
    const int stride = gridDim.x * NT;

    for (int i = blockIdx.x * NT + tid; i < n; i += stride) {
        float4 v = in4[i];
        float4 r;
        r.x = fminf(fmaxf((v.x - blk) * m, 0.0f), 1.0f);
        r.y = fminf(fmaxf((v.y - blk) * m, 0.0f), 1.0f);
        r.z = fminf(fmaxf((v.z - blk) * m, 0.0f), 1.0f);
        r.w = fminf(fmaxf((v.w - blk) * m, 0.0f), 1.0f);
        o4[i] = r;
    }
}

// ---------------- launch ----------------
extern "C" void kernel_launch(void* const* d_in, const int* in_sizes, int n_in,
                              void* d_out, int out_size) {
    const float* img = (const float*)d_in[0];
    const float* mat = (const float*)d_in[1];
    float* out = (float*)d_out;

    dim3 gBig(CHUNKS, BATCH);
    k_yhist<<<gBig, NT>>>(img, mat);
    k_fine<<<gBig, NT>>>();
    dim3 gApply(384, BATCH);
    k_apply<<<gApply, NT>>>(img, out);
}

// round 10
// speedup vs baseline: 1.3213x; 1.0162x over previous
#include <cuda_runtime.h>

#define BATCH 16
#define HW (1 << 20)
#define BINS 8192               // 13-bit quantization, single level
#define CHUNKS 64               // yhist CTAs per batch
#define NT 256
#define APB 384                 // apply streamer CTAs per batch

// percentile ranks, n = 1048576 (linear interp):
// blk: 0.25*v[10485] + 0.75*v[10486] ; wht: 0.75*v[1038089] + 0.25*v[1038090]
#define RANK0 10485u
#define RANK1 10486u
#define RANK2 1038089u
#define RANK3 1038090u

// ---------------- device scratch ----------------
__device__ unsigned g_hist[BATCH][BINS];   // 512 KB total, L2-resident
__device__ float    g_blk[BATCH];
__device__ float    g_mult[BATCH];
__device__ unsigned g_flag[BATCH];         // select published flags

// ------------- kernel 1: 13-bit luma histogram (no luma scratch) -------------
__global__ void __launch_bounds__(NT) k_yhist(const float* __restrict__ img,
                                              const float* __restrict__ mat) {
    __shared__ unsigned sh[BINS];
    const int b = blockIdx.y;
    const int chunk = blockIdx.x;
    const int tid = threadIdx.x;

    // clear flags for this replay (runs before k_apply on the stream)
    if (blockIdx.x == 0 && blockIdx.y == 0 && tid < BATCH) g_flag[tid] = 0u;

    for (int j = tid; j < BINS; j += NT) sh[j] = 0u;
    __syncthreads();

    const float c0 = mat[0], c1 = mat[1], c2 = mat[2];
    const size_t base = (size_t)b * 3 * HW;
    const float4* __restrict__ R  = (const float4*)(img + base);
    const float4* __restrict__ G  = (const float4*)(img + base + HW);
    const float4* __restrict__ Bc = (const float4*)(img + base + 2 * (size_t)HW);

    const int per_cta = (HW / 4) / CHUNKS;   // 4096 float4
    const int off = chunk * per_cta;

    #pragma unroll 4
    for (int i = tid; i < per_cta; i += NT) {
        float4 r = R[off + i];
        float4 g = G[off + i];
        float4 v = Bc[off + i];
        float y0 = c0 * r.x + c1 * g.x + c2 * v.x;
        float y1 = c0 * r.y + c1 * g.y + c2 * v.y;
        float y2 = c0 * r.z + c1 * g.z + c2 * v.z;
        float y3 = c0 * r.w + c1 * g.w + c2 * v.w;
        unsigned q0 = min((unsigned)(y0 * 8192.0f), BINS - 1u);
        unsigned q1 = min((unsigned)(y1 * 8192.0f), BINS - 1u);
        unsigned q2 = min((unsigned)(y2 * 8192.0f), BINS - 1u);
        unsigned q3 = min((unsigned)(y3 * 8192.0f), BINS - 1u);
        atomicAdd(&sh[q0], 1u);
        atomicAdd(&sh[q1], 1u);
        atomicAdd(&sh[q2], 1u);
        atomicAdd(&sh[q3], 1u);
    }
    __syncthreads();

    for (int j = tid; j < BINS; j += NT) {
        unsigned v = sh[j];
        if (v) atomicAdd(&g_hist[b][j], v);
    }
}

// ------------- kernel 2: 1D grid = 16 producers (select) + 6144 streamers (apply) -------------
__global__ void __launch_bounds__(NT) k_apply(const float* __restrict__ img,
                                              float* __restrict__ out) {
    const int tid = threadIdx.x;

    if (blockIdx.x < BATCH) {
        // ================= producer: select for batch b =================
        const int b = blockIdx.x;
        __shared__ unsigned warp_tot[NT / 32];
        __shared__ float s_vals[4];
        const unsigned* __restrict__ h = g_hist[b];
        const int W = BINS / NT;              // 32 bins per thread
        const int sbase = tid * W;
        const int lane = tid & 31;
        const int wid = tid >> 5;

        unsigned bins[BINS / NT];
        unsigned local = 0;
        #pragma unroll
        for (int j = 0; j < W; j++) { bins[j] = __ldcg(h + sbase + j); local += bins[j]; }

        // block inclusive scan of per-thread totals
        unsigned p = local;
        #pragma unroll
        for (int d = 1; d < 32; d <<= 1) {
            unsigned o = __shfl_up_sync(0xffffffffu, p, d);
            if (lane >= d) p += o;
        }
        if (lane == 31) warp_tot[wid] = p;
        __syncthreads();
        if (tid == 0) {
            unsigned cum = 0;
            #pragma unroll
            for (int k = 0; k < NT / 32; k++) { unsigned t = warp_tot[k]; warp_tot[k] = cum; cum += t; }
        }
        __syncthreads();
        const unsigned pre = p - local + warp_tot[wid];

        const unsigned ranks[4] = {RANK0, RANK1, RANK2, RANK3};
        #pragma unroll
        for (int t = 0; t < 4; t++) {
            unsigned r = ranks[t];
            if (r >= pre && r < pre + local) {
                unsigned cum = pre;
                #pragma unroll
                for (int j = 0; j < W; j++) {
                    unsigned c = bins[j];
                    if (r < cum + c) {
                        s_vals[t] = ((float)(sbase + j) + 0.5f) * (1.0f / 8192.0f);
                        break;
                    }
                    cum += c;
                }
            }
        }
        __syncthreads();
        if (tid == 0) {
            float blk = 0.25f * s_vals[0] + 0.75f * s_vals[1];
            float wht = 0.75f * s_vals[2] + 0.25f * s_vals[3];
            g_blk[b] = blk;
            g_mult[b] = fminf(1.0f / (wht - blk), 1.5f);
            __threadfence();                  // 16 CTAs total: negligible
            g_flag[b] = 1u;
        }
        // zero this batch's hist for the next replay (sole writer, no race)
        for (int j = tid; j < BINS; j += NT) g_hist[b][j] = 0u;
        return;
    }

    // ================= streamer: clip((img-blk)*mult) =================
    const int s = blockIdx.x - BATCH;
    const int b = s / APB;
    const int chunk = s % APB;

    if (tid == 0) {
        while (*(volatile unsigned*)&g_flag[b] == 0u) __nanosleep(64);
    }
    __syncthreads();
    const float blk = __ldcg(&g_blk[b]);
    const float m = __ldcg(&g_mult[b]);

    const size_t base = (size_t)b * 3 * (HW / 4);
    const float4* __restrict__ in4 = (const float4*)img + base;
    float4* __restrict__ o4 = (float4*)out + base;
    const int n = 3 * (HW / 4);               // 786432 float4 per batch
    const int stride = APB * NT;

    for (int i = chunk * NT + tid; i < n; i += stride) {
        float4 v = in4[i];
        float4 r;
        r.x = fminf(fmaxf((v.x - blk) * m, 0.0f), 1.0f);
        r.y = fminf(fmaxf((v.y - blk) * m, 0.0f), 1.0f);
        r.z = fminf(fmaxf((v.z - blk) * m, 0.0f), 1.0f);
        r.w = fminf(fmaxf((v.w - blk) * m, 0.0f), 1.0f);
        o4[i] = r;
    }
}

// ---------------- launch ----------------
extern "C" void kernel_launch(void* const* d_in, const int* in_sizes, int n_in,
                              void* d_out, int out_size) {
    const float* img = (const float*)d_in[0];
    const float* mat = (const float*)d_in[1];
    float* out = (float*)d_out;

    dim3 gHist(CHUNKS, BATCH);
    k_yhist<<<gHist, NT>>>(img, mat);
    k_apply<<<BATCH + APB * BATCH, NT>>>(img, out);
}

// round 11
// speedup vs baseline: 1.5477x; 1.1713x over previous
#include <cuda_runtime.h>

#define BATCH 16
#define HW (1 << 20)
#define BINS 4096               // 12-bit quantization, single level
#define CHUNKS 64               // yhist CTAs per batch
#define NT 256
#define APB 384                 // apply streamer CTAs per batch

// percentile ranks, n = 1048576 (linear interp):
// blk: 0.25*v[10485] + 0.75*v[10486] ; wht: 0.75*v[1038089] + 0.25*v[1038090]
#define RANK0 10485u
#define RANK1 10486u
#define RANK2 1038089u
#define RANK3 1038090u

// ---------------- device scratch ----------------
__device__ unsigned g_hist[BATCH][BINS];   // 256 KB total, L2-resident
__device__ float    g_blk[BATCH];
__device__ float    g_mult[BATCH];
__device__ unsigned g_flag[BATCH];         // select published flags

// ------------- kernel 1: 12-bit luma histogram (no luma scratch) -------------
__global__ void __launch_bounds__(NT) k_yhist(const float* __restrict__ img,
                                              const float* __restrict__ mat) {
    __shared__ unsigned sh[BINS];
    const int b = blockIdx.y;
    const int chunk = blockIdx.x;
    const int tid = threadIdx.x;

    // clear flags for this replay (k_yhist completes before k_apply starts)
    if (blockIdx.x == 0 && blockIdx.y == 0 && tid < BATCH) g_flag[tid] = 0u;

    for (int j = tid; j < BINS; j += NT) sh[j] = 0u;
    __syncthreads();

    const float c0 = mat[0], c1 = mat[1], c2 = mat[2];
    const size_t base = (size_t)b * 3 * HW;
    const float4* __restrict__ R  = (const float4*)(img + base);
    const float4* __restrict__ G  = (const float4*)(img + base + HW);
    const float4* __restrict__ Bc = (const float4*)(img + base + 2 * (size_t)HW);

    const int per_cta = (HW / 4) / CHUNKS;   // 4096 float4
    const int off = chunk * per_cta;

    #pragma unroll 4
    for (int i = tid; i < per_cta; i += NT) {
        float4 r = R[off + i];
        float4 g = G[off + i];
        float4 v = Bc[off + i];
        float y0 = c0 * r.x + c1 * g.x + c2 * v.x;
        float y1 = c0 * r.y + c1 * g.y + c2 * v.y;
        float y2 = c0 * r.z + c1 * g.z + c2 * v.z;
        float y3 = c0 * r.w + c1 * g.w + c2 * v.w;
        unsigned q0 = min((unsigned)(y0 * 4096.0f), BINS - 1u);
        unsigned q1 = min((unsigned)(y1 * 4096.0f), BINS - 1u);
        unsigned q2 = min((unsigned)(y2 * 4096.0f), BINS - 1u);
        unsigned q3 = min((unsigned)(y3 * 4096.0f), BINS - 1u);
        atomicAdd(&sh[q0], 1u);
        atomicAdd(&sh[q1], 1u);
        atomicAdd(&sh[q2], 1u);
        atomicAdd(&sh[q3], 1u);
    }
    __syncthreads();

    for (int j = tid; j < BINS; j += NT) {
        unsigned v = sh[j];
        if (v) atomicAdd(&g_hist[b][j], v);
    }
}

// ------------- kernel 2: 1D grid = 16 producers (select) + 6144 streamers (apply) -------------
// Producer branch deliberately keeps NO per-thread arrays (register parity with streamers).
__global__ void __launch_bounds__(NT) k_apply(const float* __restrict__ img,
                                              float* __restrict__ out) {
    const int tid = threadIdx.x;

    if (blockIdx.x < BATCH) {
        // ================= producer: select for batch b =================
        const int b = blockIdx.x;
        __shared__ unsigned warp_tot[NT / 32];
        __shared__ float s_vals[4];
        const unsigned* __restrict__ h = g_hist[b];
        const int W = BINS / NT;              // 16 bins per thread
        const int sbase = tid * W;
        const int lane = tid & 31;
        const int wid = tid >> 5;

        // pass 1: per-thread total only (no register array)
        unsigned local = 0;
        for (int j = 0; j < W; j++) local += __ldcg(h + sbase + j);

        // block inclusive scan of per-thread totals
        unsigned p = local;
        #pragma unroll
        for (int d = 1; d < 32; d <<= 1) {
            unsigned o = __shfl_up_sync(0xffffffffu, p, d);
            if (lane >= d) p += o;
        }
        if (lane == 31) warp_tot[wid] = p;
        __syncthreads();
        if (tid == 0) {
            unsigned cum = 0;
            #pragma unroll
            for (int k = 0; k < NT / 32; k++) { unsigned t = warp_tot[k]; warp_tot[k] = cum; cum += t; }
        }
        __syncthreads();
        const unsigned pre = p - local + warp_tot[wid];

        // pass 2: only the owning thread re-walks its 16 bins (L2 hits)
        const unsigned ranks[4] = {RANK0, RANK1, RANK2, RANK3};
        #pragma unroll
        for (int t = 0; t < 4; t++) {
            unsigned r = ranks[t];
            if (r >= pre && r < pre + local) {
                unsigned cum = pre;
                for (int j = 0; j < W; j++) {
                    unsigned c = __ldcg(h + sbase + j);
                    if (r < cum + c) {
                        s_vals[t] = ((float)(sbase + j) + 0.5f) * (1.0f / 4096.0f);
                        break;
                    }
                    cum += c;
                }
            }
        }
        __syncthreads();
        if (tid == 0) {
            float blk = 0.25f * s_vals[0] + 0.75f * s_vals[1];
            float wht = 0.75f * s_vals[2] + 0.25f * s_vals[3];
            g_blk[b] = blk;
            g_mult[b] = fminf(1.0f / (wht - blk), 1.5f);
            __threadfence();                  // 16 CTAs total: negligible
            g_flag[b] = 1u;
        }
        // zero this batch's hist for the next replay (sole writer, no race)
        for (int j = tid; j < BINS; j += NT) g_hist[b][j] = 0u;
        return;
    }

    // ================= streamer: clip((img-blk)*mult) =================
    const int s = blockIdx.x - BATCH;
    const int b = s / APB;
    const int chunk = s % APB;

    if (tid == 0) {
        while (*(volatile unsigned*)&g_flag[b] == 0u) __nanosleep(64);
    }
    __syncthreads();
    const float blk = __ldcg(&g_blk[b]);
    const float m = __ldcg(&g_mult[b]);

    const size_t base = (size_t)b * 3 * (HW / 4);
    const float4* __restrict__ in4 = (const float4*)img + base;
    float4* __restrict__ o4 = (float4*)out + base;
    const int n = 3 * (HW / 4);               // 786432 float4 per batch
    const int stride = APB * NT;

    for (int i = chunk * NT + tid; i < n; i += stride) {
        float4 v = in4[i];
        float4 r;
        r.x = fminf(fmaxf((v.x - blk) * m, 0.0f), 1.0f);
        r.y = fminf(fmaxf((v.y - blk) * m, 0.0f), 1.0f);
        r.z = fminf(fmaxf((v.z - blk) * m, 0.0f), 1.0f);
        r.w = fminf(fmaxf((v.w - blk) * m, 0.0f), 1.0f);
        o4[i] = r;
    }
}

// ---------------- launch ----------------
extern "C" void kernel_launch(void* const* d_in, const int* in_sizes, int n_in,
                              void* d_out, int out_size) {
    const float* img = (const float*)d_in[0];
    const float* mat = (const float*)d_in[1];
    float* out = (float*)d_out;

    dim3 gHist(CHUNKS, BATCH);
    k_yhist<<<gHist, NT>>>(img, mat);
    k_apply<<<BATCH + APB * BATCH, NT>>>(img, out);
}

// round 12
// speedup vs baseline: 1.6148x; 1.0434x over previous
#include <cuda_runtime.h>

#define BATCH 16
#define HW (1 << 20)
#define BINS 2048               // 11-bit quantization, single level
#define CHUNKS 32               // yhist CTAs per batch
#define NT 256
#define APB 384                 // apply CTAs per batch

// percentile ranks, n = 1048576 (linear interp):
// blk: 0.25*v[10485] + 0.75*v[10486] ; wht: 0.75*v[1038089] + 0.25*v[1038090]
#define RANK0 10485u
#define RANK1 10486u
#define RANK2 1038089u
#define RANK3 1038090u

// ---------------- device scratch ----------------
__device__ unsigned g_hist[BATCH][BINS];   // 128 KB total, L2-resident
__device__ float    g_blk[BATCH];
__device__ float    g_mult[BATCH];

// ------------- kernel 1: 11-bit luma histogram; chunk-0 CTA per batch selects -------------
__global__ void __launch_bounds__(NT) k_yhist(const float* __restrict__ img,
                                              const float* __restrict__ mat) {
    __shared__ unsigned sh[BINS];
    __shared__ unsigned s_red[NT / 32];
    __shared__ unsigned s_total;
    __shared__ float s_vals[4];
    const int b = blockIdx.y;
    const int chunk = blockIdx.x;
    const int tid = threadIdx.x;
    const int lane = tid & 31;
    const int wid = tid >> 5;

    for (int j = tid; j < BINS; j += NT) sh[j] = 0u;
    __syncthreads();

    const float c0 = mat[0], c1 = mat[1], c2 = mat[2];
    const size_t base = (size_t)b * 3 * HW;
    const float4* __restrict__ R  = (const float4*)(img + base);
    const float4* __restrict__ G  = (const float4*)(img + base + HW);
    const float4* __restrict__ Bc = (const float4*)(img + base + 2 * (size_t)HW);

    const int per_cta = (HW / 4) / CHUNKS;   // 8192 float4
    const int off = chunk * per_cta;

    #pragma unroll 4
    for (int i = tid; i < per_cta; i += NT) {
        float4 r = R[off + i];
        float4 g = G[off + i];
        float4 v = Bc[off + i];
        float y0 = c0 * r.x + c1 * g.x + c2 * v.x;
        float y1 = c0 * r.y + c1 * g.y + c2 * v.y;
        float y2 = c0 * r.z + c1 * g.z + c2 * v.z;
        float y3 = c0 * r.w + c1 * g.w + c2 * v.w;
        unsigned q0 = min((unsigned)(y0 * 2048.0f), BINS - 1u);
        unsigned q1 = min((unsigned)(y1 * 2048.0f), BINS - 1u);
        unsigned q2 = min((unsigned)(y2 * 2048.0f), BINS - 1u);
        unsigned q3 = min((unsigned)(y3 * 2048.0f), BINS - 1u);
        atomicAdd(&sh[q0], 1u);
        atomicAdd(&sh[q1], 1u);
        atomicAdd(&sh[q2], 1u);
        atomicAdd(&sh[q3], 1u);
    }
    __syncthreads();

    for (int j = tid; j < BINS; j += NT) {
        unsigned v = sh[j];
        if (v) atomicAdd(&g_hist[b][j], v);
    }

    if (blockIdx.x != 0) return;

    // ================ producer tail (16 CTAs): fence-free completion + select ================
    const unsigned* __restrict__ h = g_hist[b];
    const int W = BINS / NT;                  // 8 bins per thread
    const int sbase = tid * W;
    unsigned bins[BINS / NT];
    unsigned local;

    // spin: monotone counters sum to exactly HW only when every flush is visible
    for (;;) {
        local = 0;
        #pragma unroll
        for (int j = 0; j < W; j++) { bins[j] = __ldcg(h + sbase + j); local += bins[j]; }
        // block reduce
        unsigned s = local;
        #pragma unroll
        for (int d = 16; d > 0; d >>= 1) s += __shfl_down_sync(0xffffffffu, s, d);
        if (lane == 0) s_red[wid] = s;
        __syncthreads();
        if (tid == 0) {
            unsigned tot = 0;
            #pragma unroll
            for (int k = 0; k < NT / 32; k++) tot += s_red[k];
            s_total = tot;
        }
        __syncthreads();
        if (s_total == (unsigned)HW) break;
        __nanosleep(128);
        __syncthreads();
    }

    // block exclusive scan of per-thread totals
    unsigned p = local;
    #pragma unroll
    for (int d = 1; d < 32; d <<= 1) {
        unsigned o = __shfl_up_sync(0xffffffffu, p, d);
        if (lane >= d) p += o;
    }
    if (lane == 31) s_red[wid] = p;
    __syncthreads();
    if (tid == 0) {
        unsigned cum = 0;
        #pragma unroll
        for (int k = 0; k < NT / 32; k++) { unsigned t = s_red[k]; s_red[k] = cum; cum += t; }
    }
    __syncthreads();
    const unsigned pre = p - local + s_red[wid];

    const unsigned ranks[4] = {RANK0, RANK1, RANK2, RANK3};
    #pragma unroll
    for (int t = 0; t < 4; t++) {
        unsigned r = ranks[t];
        if (r >= pre && r < pre + local) {
            unsigned cum = pre;
            #pragma unroll
            for (int j = 0; j < W; j++) {
                unsigned c = bins[j];
                if (r < cum + c) {
                    s_vals[t] = ((float)(sbase + j) + 0.5f) * (1.0f / 2048.0f);
                    break;
                }
                cum += c;
            }
        }
    }
    __syncthreads();
    if (tid == 0) {
        float blk = 0.25f * s_vals[0] + 0.75f * s_vals[1];
        float wht = 0.75f * s_vals[2] + 0.25f * s_vals[3];
        g_blk[b] = blk;
        g_mult[b] = fminf(1.0f / (wht - blk), 1.5f);
    }
    // zero this batch's hist for the next replay (sole writer; batch hist is final)
    for (int j = tid; j < BINS; j += NT) g_hist[b][j] = 0u;
}

// ------------- kernel 2: pure streamer: out = clip((img - blk)*mult, 0, 1) -------------
__global__ void __launch_bounds__(NT) k_apply(const float* __restrict__ img,
                                              float* __restrict__ out) {
    const int b = blockIdx.y;
    const float blk = g_blk[b];
    const float m = g_mult[b];

    const size_t base = (size_t)b * 3 * (HW / 4);
    const float4* __restrict__ in4 = (const float4*)img + base;
    float4* __restrict__ o4 = (float4*)out + base;
    const int n = 3 * (HW / 4);               // 786432 float4 per batch
    const int stride = gridDim.x * NT;

    for (int i = blockIdx.x * NT + threadIdx.x; i < n; i += stride) {
        float4 v = in4[i];
        float4 r;
        r.x = fminf(fmaxf((v.x - blk) * m, 0.0f), 1.0f);
        r.y = fminf(fmaxf((v.y - blk) * m, 0.0f), 1.0f);
        r.z = fminf(fmaxf((v.z - blk) * m, 0.0f), 1.0f);
        r.w = fminf(fmaxf((v.w - blk) * m, 0.0f), 1.0f);
        o4[i] = r;
    }
}

// ---------------- launch ----------------
extern "C" void kernel_launch(void* const* d_in, const int* in_sizes, int n_in,
                              void* d_out, int out_size) {
    const float* img = (const float*)d_in[0];
    const float* mat = (const float*)d_in[1];
    float* out = (float*)d_out;

    dim3 gHist(CHUNKS, BATCH);
    k_yhist<<<gHist, NT>>>(img, mat);
    dim3 gApply(APB, BATCH);
    k_apply<<<gApply, NT>>>(img, out);
}